// round 8
// baseline (speedup 1.0000x reference)
#include <cuda_runtime.h>

#define BB   256
#define TT   1024
#define SS   7
#define HH   64
#define LL   4
#define OO   3
#define UU   4          // timesteps per epoch
#define BETA 0.8f
#define TH   1.0f

#define NEPOCH (TT / UU)   // 256 productive epochs per layer

// Named-barrier rendezvous (two-sided). id 0 is reserved for __syncthreads.
__device__ __forceinline__ void nbar(int id, int nthreads) {
    asm volatile("bar.sync %0, %1;" :: "r"(id), "r"(nthreads) : "memory");
}

// One CTA per batch element. Threads 0..255: (layer l = tid>>6, unit h = tid&63),
// each owns membrane m[l][h] and its 64-float weight row in registers.
// Warp 8 (lanes 0..2): output-layer dot products.
//
// Pipeline across epochs of UU=4 timesteps, but synchronized PAIRWISE instead
// of globally: barrier B_l (named id l+1) is a two-sided rendezvous between
// layer l (producer, syncs at END of its epoch e) and layer l+1 / out warp
// (consumer, syncs at START of its epoch e+1). With double-buffered spike
// storage this is sufficient: after rendezvous k the producer is exactly one
// epoch ahead and overwrites the buffer the consumer drained before arriving.
// No global convergence -> light/heavy warp imbalance no longer serializes.
// Per-timestep math identical to the 385us R7 kernel (same accumulation order).
__global__ __launch_bounds__(288, 2)
void snn_async_kernel(const float* __restrict__ x,
                      const float* __restrict__ hidden0,
                      const float* __restrict__ w1,
                      const float* __restrict__ b1,
                      const float* __restrict__ w_h,
                      const float* __restrict__ b_h,
                      const float* __restrict__ w_out,
                      const float* __restrict__ b_out,
                      float* __restrict__ out_outputs,   // [B,T,OO]
                      float* __restrict__ out_hidden,    // [B,T,LL,HH]
                      float* __restrict__ out_xcopy)     // [B,T,SS]
{
    const int b   = blockIdx.x;
    const int tid = threadIdx.x;

    __shared__ __align__(16) float spk[2][LL][UU][HH];   // double-buffered epochs

    // ---- copy this batch's x slice to the output buffer (coalesced float4) ----
    {
        const float4* xs4 = (const float4*)(x + (size_t)b * TT * SS);
        float4*       xo4 = (float4*)(out_xcopy + (size_t)b * TT * SS);
        const int n4 = TT * SS / 4;  // 1792
        for (int i = tid; i < n4; i += blockDim.x) xo4[i] = xs4[i];
    }

    const int  l        = tid >> 6;          // layer for tid<256
    const int  h        = tid & 63;
    const bool is_layer = (tid < LL * HH);

    float wrow[HH];
    float w0[SS];
    float bias = 0.0f;
    float m    = 0.0f;

    if (is_layer) {
        m = hidden0[(size_t)b * TT * LL * HH + (size_t)l * HH + h];
        if (l == 0) {
            #pragma unroll
            for (int k = 0; k < SS; k++) w0[k] = w1[h * SS + k];
            bias = b1[h];
        } else {
            #pragma unroll
            for (int i = 0; i < HH; i++) wrow[i] = w_h[((size_t)(l - 1) * HH + h) * HH + i];
            bias = b_h[(l - 1) * HH + h];
        }
    } else if (tid < LL * HH + OO) {
        const int j = tid - LL * HH;
        #pragma unroll
        for (int i = 0; i < HH; i++) wrow[i] = w_out[j * HH + i];
        bias = b_out[j];
    }

    __syncthreads();   // nothing shared yet, but cleanly separates setup

    if (is_layer) {
        const float* xrow   = x + (size_t)b * TT * SS;
        float*       hidptr = out_hidden + (size_t)b * TT * LL * HH + l * HH + h;
        const int    upId   = l;        // B_{l-1} (consumer side), valid for l>0
        const int    dnId   = l + 1;    // B_l     (producer side)
        const int    dnCnt  = (l == LL - 1) ? 96 : 128;

        for (int e = l; e < l + NEPOCH; e++) {
            const int buf = e & 1;
            if (l > 0) nbar(upId, 128);          // upstream data ready

            float c[UU];
            if (l == 0) {
                #pragma unroll
                for (int k = 0; k < UU; k++) {
                    float acc = bias;
                    #pragma unroll
                    for (int j = 0; j < SS; j++)
                        acc = fmaf(xrow[k * SS + j], w0[j], acc);
                    c[k] = acc;
                }
                xrow += UU * SS;
            } else {
                #pragma unroll
                for (int k = 0; k < UU; k++) {
                    const float* sp = spk[buf ^ 1][l - 1][k];
                    float a0 = 0.f, a1 = 0.f, a2 = 0.f, a3 = 0.f;
                    #pragma unroll
                    for (int i = 0; i < HH; i += 4) {
                        float4 sv = *(const float4*)(sp + i);
                        a0 = fmaf(sv.x, wrow[i + 0], a0);
                        a1 = fmaf(sv.y, wrow[i + 1], a1);
                        a2 = fmaf(sv.z, wrow[i + 2], a2);
                        a3 = fmaf(sv.w, wrow[i + 3], a3);
                    }
                    c[k] = bias + ((a0 + a1) + (a2 + a3));
                }
            }
            // sequential membrane chain over the 4 timesteps
            #pragma unroll
            for (int k = 0; k < UU; k++) {
                const float reset = (m > TH) ? TH : 0.0f;
                const float m_new = fmaf(BETA, m, c[k]) - reset;
                m = m_new;
                spk[buf][l][k][h] = (m_new > TH) ? 1.0f : 0.0f;
                hidptr[(size_t)k * (LL * HH)] = m_new;
            }
            hidptr += (size_t)UU * LL * HH;

            nbar(dnId, dnCnt);                   // publish to downstream
        }
    } else {
        // warp 8: output layer. All 32 lanes run the loop & barrier; lanes 0..2 compute.
        const int  j      = tid - LL * HH;       // 0..31
        const bool active = (j < OO);
        float*     outptr = out_outputs + (size_t)b * TT * OO + j;

        for (int e = LL; e < LL + NEPOCH; e++) {
            const int buf = e & 1;
            nbar(LL, 96);                        // layer-3 data ready
            if (active) {
                #pragma unroll
                for (int k = 0; k < UU; k++) {
                    const float* sp = spk[buf ^ 1][LL - 1][k];
                    float a0 = 0.f, a1 = 0.f, a2 = 0.f, a3 = 0.f;
                    #pragma unroll
                    for (int i = 0; i < HH; i += 4) {
                        float4 sv = *(const float4*)(sp + i);
                        a0 = fmaf(sv.x, wrow[i + 0], a0);
                        a1 = fmaf(sv.y, wrow[i + 1], a1);
                        a2 = fmaf(sv.z, wrow[i + 2], a2);
                        a3 = fmaf(sv.w, wrow[i + 3], a3);
                    }
                    outptr[k * OO] = bias + ((a0 + a1) + (a2 + a3));
                }
                outptr += UU * OO;
            }
        }
    }
}

extern "C" void kernel_launch(void* const* d_in, const int* in_sizes, int n_in,
                              void* d_out, int out_size) {
    // metadata order: x, hidden_states, prev_obs, w1, b1, w_h, b_h, w_out, b_out
    const float* x       = (const float*)d_in[0];
    const float* hidden0 = (const float*)d_in[1];
    // d_in[2] = prev_obs (unused by reference)
    const float* w1      = (const float*)d_in[3];
    const float* b1      = (const float*)d_in[4];
    const float* w_h     = (const float*)d_in[5];
    const float* b_h     = (const float*)d_in[6];
    const float* w_out   = (const float*)d_in[7];
    const float* b_out   = (const float*)d_in[8];

    float* out_outputs = (float*)d_out;                                  // B*T*OO
    float* out_hidden  = out_outputs + (size_t)BB * TT * OO;             // B*T*LL*HH
    float* out_xcopy   = out_hidden + (size_t)BB * TT * LL * HH;         // B*T*SS

    snn_async_kernel<<<BB, 288>>>(x, hidden0, w1, b1, w_h, b_h, w_out, b_out,
                                  out_outputs, out_hidden, out_xcopy);
}

// round 9
// speedup vs baseline: 1.1040x; 1.1040x over previous
#include <cuda_runtime.h>

#define BB   256
#define TT   1024
#define SS   7
#define HH   64
#define LL   4
#define OO   3
#define UU   4
#define BETA 0.8f
#define TH   1.0f
#define NEPOCH (TT / UU)      // 256
#define ROWF   68             // padded spike row: half0 floats [0,32) at byte 0,
                              // half1 floats [32,64) at byte 144 -> bank-disjoint

// 32-element dot product: spike chunk (16B-aligned) x register weight row.
__device__ __forceinline__ float dot32(const float* __restrict__ sp,
                                       const float* __restrict__ wrow) {
    float a0 = 0.f, a1 = 0.f;
    #pragma unroll
    for (int i = 0; i < 8; i++) {
        float4 sv = *(const float4*)(sp + 4 * i);
        a0 = fmaf(sv.x, wrow[4 * i + 0], a0);
        a1 = fmaf(sv.y, wrow[4 * i + 1], a1);
        a0 = fmaf(sv.z, wrow[4 * i + 2], a0);
        a1 = fmaf(sv.w, wrow[4 * i + 3], a1);
    }
    return a0 + a1;
}

// One CTA per batch element, 544 threads.
// tids 0..511: layer threads. l = tid>>7 (4 warps per layer), q = tid&127,
//   unit h = q>>1, half = q&1. Each thread holds HALF a weight row (32 regs),
//   computes a 32-FMA partial, combines with its lane-pair via shfl_xor(1).
//   Both halves run the membrane chain redundantly (identical values); only
//   half==0 stores spikes / hidden state.
// tids 512..517: output layer, same half-split (3 outputs x 2 halves).
// Layers pipelined across epochs of UU=4 timesteps, double-buffered spikes,
// one __syncthreads per epoch. 2 CTAs/SM -> 34 warps (vs 18 before).
__global__ __launch_bounds__(544, 2)
void snn_split_kernel(const float* __restrict__ x,
                      const float* __restrict__ hidden0,
                      const float* __restrict__ w1,
                      const float* __restrict__ b1,
                      const float* __restrict__ w_h,
                      const float* __restrict__ b_h,
                      const float* __restrict__ w_out,
                      const float* __restrict__ b_out,
                      float* __restrict__ out_outputs,   // [B,T,OO]
                      float* __restrict__ out_hidden,    // [B,T,LL,HH]
                      float* __restrict__ out_xcopy)     // [B,T,SS]
{
    const int b   = blockIdx.x;
    const int tid = threadIdx.x;

    __shared__ __align__(16) float spk[2][LL][UU][ROWF];

    // ---- copy this batch's x slice to the output buffer (coalesced float4) ----
    {
        const float4* xs4 = (const float4*)(x + (size_t)b * TT * SS);
        float4*       xo4 = (float4*)(out_xcopy + (size_t)b * TT * SS);
        const int n4 = TT * SS / 4;  // 1792
        for (int i = tid; i < n4; i += blockDim.x) xo4[i] = xs4[i];
    }

    const bool is_layer = (tid < LL * HH * 2);           // 512
    const bool is_out   = (tid >= 512) && (tid < 512 + 2 * OO);
    const int  l    = tid >> 7;          // valid for layer threads
    const int  q    = tid & 127;
    const int  h    = q >> 1;
    const int  half = q & 1;

    float wrow[32];
    float bias = 0.0f;
    float m    = 0.0f;
    int   hoff = 0;                      // padded spike-row offset for unit h

    if (is_layer) {
        m    = hidden0[(size_t)b * TT * LL * HH + (size_t)l * HH + h];
        hoff = h + ((h >= 32) ? 4 : 0);
        if (l == 0) {
            bias = b1[h];
            // half0: elements 0..3 ; half1: elements 4..6
            wrow[0] = w1[h * SS + half * 4 + 0];
            wrow[1] = w1[h * SS + half * 4 + 1];
            wrow[2] = w1[h * SS + half * 4 + 2];
            wrow[3] = half ? 0.0f : w1[h * SS + 3];
        } else {
            const float* row = w_h + ((size_t)(l - 1) * HH + h) * HH + half * 32;
            #pragma unroll
            for (int i = 0; i < 32; i++) wrow[i] = row[i];
            bias = b_h[(l - 1) * HH + h];
        }
    } else if (is_out) {
        const int oj = (tid - 512) >> 1;
        const int oh = (tid - 512) & 1;
        const float* row = w_out + (size_t)oj * HH + oh * 32;
        #pragma unroll
        for (int i = 0; i < 32; i++) wrow[i] = row[i];
        bias = b_out[oj];
    }

    __syncthreads();

    const float* xrow   = x + (size_t)b * TT * SS;
    float*       hidptr = out_hidden + (size_t)b * TT * LL * HH
                          + (is_layer ? (l * HH + h) : 0);
    float*       outptr = out_outputs + (size_t)b * TT * OO
                          + (is_out ? ((tid - 512) >> 1) : 0);

    int buf = 0;
    for (int e = 0; e < NEPOCH + LL; e++) {
        if (is_layer) {
            if (e >= l && e < l + NEPOCH) {
                float p[UU];
                if (l == 0) {
                    // partial over this half's 3-or-4 x elements
                    #pragma unroll
                    for (int k = 0; k < UU; k++) {
                        const float* xr = xrow + k * SS + half * 4;
                        float a = 0.f;
                        a = fmaf(xr[0], wrow[0], a);
                        a = fmaf(xr[1], wrow[1], a);
                        a = fmaf(xr[2], wrow[2], a);
                        if (!half) a = fmaf(xr[3], wrow[3], a);
                        p[k] = a;
                    }
                    xrow += UU * SS;
                } else {
                    #pragma unroll
                    for (int k = 0; k < UU; k++)
                        p[k] = dot32(&spk[buf ^ 1][l - 1][k][half * 36], wrow);
                }
                // combine halves + sequential membrane chain
                #pragma unroll
                for (int k = 0; k < UU; k++) {
                    const float tot = p[k] + __shfl_xor_sync(0xffffffffu, p[k], 1);
                    const float c   = bias + tot;
                    const float reset = (m > TH) ? TH : 0.0f;
                    const float m_new = fmaf(BETA, m, c) - reset;
                    m = m_new;
                    if (!half) {
                        spk[buf][l][k][hoff] = (m_new > TH) ? 1.0f : 0.0f;
                        hidptr[(size_t)k * (LL * HH)] = m_new;
                    }
                }
                hidptr += (size_t)UU * LL * HH;
            }
        } else if (is_out) {
            if (e >= LL) {
                const int oh = (tid - 512) & 1;
                #pragma unroll
                for (int k = 0; k < UU; k++) {
                    float pk = dot32(&spk[buf ^ 1][LL - 1][k][oh * 36], wrow);
                    float tot = pk + __shfl_xor_sync(0x3fu, pk, 1);
                    if (!oh) outptr[k * OO] = bias + tot;
                }
                outptr += UU * OO;
            }
        }
        __syncthreads();
        buf ^= 1;
    }
}

extern "C" void kernel_launch(void* const* d_in, const int* in_sizes, int n_in,
                              void* d_out, int out_size) {
    // metadata order: x, hidden_states, prev_obs, w1, b1, w_h, b_h, w_out, b_out
    const float* x       = (const float*)d_in[0];
    const float* hidden0 = (const float*)d_in[1];
    // d_in[2] = prev_obs (unused by reference)
    const float* w1      = (const float*)d_in[3];
    const float* b1      = (const float*)d_in[4];
    const float* w_h     = (const float*)d_in[5];
    const float* b_h     = (const float*)d_in[6];
    const float* w_out   = (const float*)d_in[7];
    const float* b_out   = (const float*)d_in[8];

    float* out_outputs = (float*)d_out;                                  // B*T*OO
    float* out_hidden  = out_outputs + (size_t)BB * TT * OO;             // B*T*LL*HH
    float* out_xcopy   = out_hidden + (size_t)BB * TT * LL * HH;         // B*T*SS

    snn_split_kernel<<<BB, 544>>>(x, hidden0, w1, b1, w_h, b_h, w_out, b_out,
                                  out_outputs, out_hidden, out_xcopy);
}